// round 16
// baseline (speedup 1.0000x reference)
#include <cuda_runtime.h>
#include <cuda_fp16.h>
#include <mma.h>
#include <cstdint>

using namespace nvcuda;

// ======================= problem constants =======================
#define C_DIM 128
#define MAX_N 131072
#define MAX_K 512
#define EPS 1e-8f
#define NTHREADS 512
#define NGROUPS 8              // 8 independent 2-warp groups
#define BMG 32                 // rows per group tile
#define BN  128                // output cols per CTA
#define LDH 136                // fp16 smem row stride (halves) = 272B

// ---- smem layout (bytes) ----
#define SM_B      0                                   // 128*272 = 34816
#define SM_A(g,b) (34816 + ((g) * 2 + (b)) * 8704)    // 16 bufs = 139264
#define SMEM_TOTAL 174080

// static scratch: normalized fp16 prototypes (128KB) + embeddings (32MB)
__device__ __half g_protoH[MAX_K * C_DIM];
__device__ __half g_embedH[MAX_N * C_DIM];

// ======================= helpers =======================
__device__ __forceinline__ uint32_t s2u(const void* p) {
    uint32_t a;
    asm("{ .reg .u64 t; cvta.to.shared.u64 t, %1; cvt.u32.u64 %0, t; }" : "=r"(a) : "l"(p));
    return a;
}
__device__ __forceinline__ void cp_async16(uint32_t dst, const void* src) {
    asm volatile("cp.async.cg.shared.global [%0], [%1], 16;" :: "r"(dst), "l"(src));
}
#define CP_COMMIT() asm volatile("cp.async.commit_group;" ::: "memory")
#define CP_WAIT0()  asm volatile("cp.async.wait_group 0;"  ::: "memory")
#define BAR_G(id)   asm volatile("bar.sync %0, 64;" :: "r"(id) : "memory")

__device__ __forceinline__ uint32_t h2u(__half2 h) {
    return *reinterpret_cast<uint32_t*>(&h);
}

// ======================= kernel 1: normalize E and P -> fp16 (one launch) =========
__global__ void row_norm_fp16_kernel(const float* __restrict__ E,
                                     const float* __restrict__ P,
                                     __half* __restrict__ embedH,
                                     __half* __restrict__ protoH,
                                     int N, int K) {
    int row = (blockIdx.x * blockDim.x + threadIdx.x) >> 5;
    int lane = threadIdx.x & 31;
    if (row >= N + K) return;
    const float* src = (row < N) ? (E + (size_t)row * C_DIM)
                                 : (P + (size_t)(row - N) * C_DIM);
    __half* dst = (row < N) ? (embedH + (size_t)row * C_DIM)
                            : (protoH + (size_t)(row - N) * C_DIM);
    float4 v = reinterpret_cast<const float4*>(src)[lane];
    float s = v.x * v.x + v.y * v.y + v.z * v.z + v.w * v.w;
#pragma unroll
    for (int o = 16; o; o >>= 1) s += __shfl_xor_sync(0xFFFFFFFFu, s, o);
    float inv = 1.0f / fmaxf(sqrtf(s), EPS);
    uint2 o2;
    o2.x = h2u(__floats2half2_rn(v.x * inv, v.y * inv));
    o2.y = h2u(__floats2half2_rn(v.z * inv, v.w * inv));
    reinterpret_cast<uint2*>(dst)[lane] = o2;
}

// ======================= kernel 2: 8-stream persistent fp16 GEMM ==================
// 8 independent 2-warp groups per CTA. Group tile: 32 rows x 128 cols; warp tile
// 32x64 (2x4 m16n16k16). A double-buffered cp.async fp16; B smem, shared.
__global__ __launch_bounds__(NTHREADS, 1)
void hsproto_gemm_kernel(float* __restrict__ out, int nRowTiles, int Kout) {
    extern __shared__ char smem[];
    const uint32_t sb = s2u(smem);
    const __half* B_h = reinterpret_cast<const __half*>(smem + SM_B);

    const int tid = threadIdx.x;
    const int g   = tid >> 6;             // group 0..7
    const int gt  = tid & 63;             // thread in group
    const int wn  = gt >> 5;              // warp in group = 64-col band 0..1
    const int colBase = blockIdx.x * BN;
    const int barid = g + 1;

    // ---- issue B tile cp.async (all 512 threads; 128 rows x 256B, 4 thr/row) ----
    {
        int rb = tid >> 2, qb = tid & 3;
        const __half* gB = g_protoH + (size_t)(colBase + rb) * C_DIM + qb * 32;
        uint32_t d = sb + SM_B + (uint32_t)(rb * 272 + qb * 64);
#pragma unroll
        for (int j = 0; j < 4; j++) cp_async16(d + j * 16, gB + j * 8);
    }

    // ---- A plumbing: 32 rows x 256B fp16 per tile; 2 thr/row, 128B each ----
    const int ra = gt >> 1, qa = gt & 1;
    const uint32_t aOff = (uint32_t)(ra * 272 + qa * 128);
    const int step = gridDim.y * NGROUPS;
    const int t0 = blockIdx.y * NGROUPS + g;

    auto ISSUE_A = [&](int t, int b) {
        const __half* gA = g_embedH + ((size_t)t * BMG + ra) * C_DIM + qa * 64;
        uint32_t d = sb + SM_A(g, b) + aOff;
#pragma unroll
        for (int j = 0; j < 8; j++) cp_async16(d + j * 16, gA + j * 8);
        CP_COMMIT();
    };
    if (t0 < nRowTiles) ISSUE_A(t0, 0);   // commits this thread's B part too
    else CP_COMMIT();

    CP_WAIT0();
    __syncthreads();                      // B + A(t0) visible everywhere

    const __half* Abuf[2] = {
        reinterpret_cast<const __half*>(smem + SM_A(g, 0)),
        reinterpret_cast<const __half*>(smem + SM_A(g, 1))
    };
    int buf = 0;

    for (int t = t0; t < nRowTiles; t += step) {
        const bool hasNext = (t + step) < nRowTiles;
        if (hasNext) ISSUE_A(t + step, buf ^ 1);   // other buffer: no WAR

        const __half* A_h = Abuf[buf];

        // ---- MMA(t): warp tile 32x64 = 2x4 m16n16k16 ----
        wmma::fragment<wmma::accumulator, 16, 16, 16, float> acc[2][4];
#pragma unroll
        for (int i = 0; i < 2; i++)
#pragma unroll
            for (int j = 0; j < 4; j++) wmma::fill_fragment(acc[i][j], 0.0f);

#pragma unroll
        for (int kk = 0; kk < 8; kk++) {
            wmma::fragment<wmma::matrix_a, 16, 16, 16, __half, wmma::row_major> a[2];
            wmma::fragment<wmma::matrix_b, 16, 16, 16, __half, wmma::col_major> b[4];
#pragma unroll
            for (int i = 0; i < 2; i++)
                wmma::load_matrix_sync(a[i], A_h + (i * 16) * LDH + kk * 16, LDH);
#pragma unroll
            for (int j = 0; j < 4; j++)
                wmma::load_matrix_sync(b[j], B_h + (wn * 64 + j * 16) * LDH + kk * 16, LDH);
#pragma unroll
            for (int i = 0; i < 2; i++)
#pragma unroll
                for (int j = 0; j < 4; j++)
                    wmma::mma_sync(acc[i][j], a[i], b[j], acc[i][j]);
        }

        // ---- epilogue: -(1-cos)^2, direct store (proven path) ----
        float* outBase = out + ((size_t)t * BMG) * Kout + colBase + wn * 64;
#pragma unroll
        for (int i = 0; i < 2; i++)
#pragma unroll
            for (int j = 0; j < 4; j++) {
#pragma unroll
                for (int e = 0; e < acc[i][j].num_elements; e++) {
                    float d = 1.0f - acc[i][j].x[e];
                    acc[i][j].x[e] = -(d * d);
                }
                wmma::store_matrix_sync(outBase + (size_t)(i * 16) * Kout + j * 16,
                                        acc[i][j], Kout, wmma::mem_row_major);
            }

        if (hasNext) {
            CP_WAIT0();                   // A(t+step) landed (this thread)
            BAR_G(barid);                 // visible group-wide; MMA A reads done
        }
        buf ^= 1;
    }
}

// ======================= launcher =======================
extern "C" void kernel_launch(void* const* d_in, const int* in_sizes, int n_in,
                              void* d_out, int out_size) {
    const float* E = (const float*)d_in[0];
    const float* P = (const float*)d_in[1];
    float* out = (float*)d_out;

    const int N = in_sizes[0] / C_DIM;   // 131072
    const int K = in_sizes[1] / C_DIM;   // 512

    __half* protoH;
    __half* embedH;
    cudaGetSymbolAddress((void**)&protoH, g_protoH);
    cudaGetSymbolAddress((void**)&embedH, g_embedH);

    row_norm_fp16_kernel<<<((N + K) * 32 + 255) / 256, 256>>>(E, P, embedH, protoH, N, K);

    static int sms = 0;
    if (!sms) {
        cudaDeviceGetAttribute(&sms, cudaDevAttrMultiProcessorCount, 0);
        cudaFuncSetAttribute(hsproto_gemm_kernel,
                             cudaFuncAttributeMaxDynamicSharedMemorySize, SMEM_TOTAL);
    }
    const int nColTiles = K / BN;                 // 4
    int stripe = sms / nColTiles;                 // 38
    if (stripe < 1) stripe = 1;
    const int nRowTiles = N / BMG;                // 4096

    dim3 grid(nColTiles, stripe);
    hsproto_gemm_kernel<<<grid, NTHREADS, SMEM_TOTAL>>>(out, nRowTiles, K);
}

// round 17
// speedup vs baseline: 1.1007x; 1.1007x over previous
#include <cuda_runtime.h>
#include <cuda_fp16.h>
#include <mma.h>
#include <cstdint>

using namespace nvcuda;

// ======================= problem constants =======================
#define C_DIM 128
#define MAX_N 131072
#define EPS 1e-8f
#define NTHREADS 512
#define NGROUPS 4
#define BMG 32                 // rows per group tile
#define BN  256                // output cols per CTA
#define LDH 136                // fp16 smem row stride (halves) = 272B

// ---- smem layout (bytes) ----
#define SM_B      0                                   // 256*272 = 69632
#define SM_A(g,b) (69632 + ((g) * 2 + (b)) * 8704)    // 8 bufs  = 69632
#define SMEM_TOTAL 139264

// static scratch: normalized fp16 embeddings (32MB)
__device__ __half g_embedH[MAX_N * C_DIM];

// ======================= helpers =======================
__device__ __forceinline__ uint32_t s2u(const void* p) {
    uint32_t a;
    asm("{ .reg .u64 t; cvta.to.shared.u64 t, %1; cvt.u32.u64 %0, t; }" : "=r"(a) : "l"(p));
    return a;
}
__device__ __forceinline__ void cp_async16(uint32_t dst, const void* src) {
    asm volatile("cp.async.cg.shared.global [%0], [%1], 16;" :: "r"(dst), "l"(src));
}
#define CP_COMMIT() asm volatile("cp.async.commit_group;" ::: "memory")
#define CP_WAIT0()  asm volatile("cp.async.wait_group 0;"  ::: "memory")
#define BAR_G(id)   asm volatile("bar.sync %0, 128;" :: "r"(id) : "memory")

__device__ __forceinline__ uint32_t h2u(__half2 h) {
    return *reinterpret_cast<uint32_t*>(&h);
}

// ======================= kernel 1: normalize E -> fp16 =======================
__global__ void e_norm_fp16_kernel(const float* __restrict__ E, int N) {
    int row = (blockIdx.x * blockDim.x + threadIdx.x) >> 5;
    int lane = threadIdx.x & 31;
    if (row >= N) return;
    float4 v = reinterpret_cast<const float4*>(E + (size_t)row * C_DIM)[lane];
    float s = v.x * v.x + v.y * v.y + v.z * v.z + v.w * v.w;
#pragma unroll
    for (int o = 16; o; o >>= 1) s += __shfl_xor_sync(0xFFFFFFFFu, s, o);
    float inv = 1.0f / fmaxf(sqrtf(s), EPS);
    uint2 o2;
    o2.x = h2u(__floats2half2_rn(v.x * inv, v.y * inv));
    o2.y = h2u(__floats2half2_rn(v.z * inv, v.w * inv));
    reinterpret_cast<uint2*>(g_embedH + (size_t)row * C_DIM)[lane] = o2;
}

// ======================= kernel 2: 4-stream persistent fp16 GEMM ==================
// R12-proven core: 4 independent 4-warp groups; group tile 32x256; warp tile 32x64;
// A double-buffered cp.async fp16; direct-store epilogue. NEW: B tile normalized
// in-prologue from raw fp32 P (saves the P-prep launch).
__global__ __launch_bounds__(NTHREADS, 1)
void hsproto_gemm_kernel(const float* __restrict__ P, float* __restrict__ out,
                         int nRowTiles, int Kout) {
    extern __shared__ char smem[];
    const uint32_t sb = s2u(smem);
    const __half* B_h = reinterpret_cast<const __half*>(smem + SM_B);

    const int tid = threadIdx.x;
    const int g   = tid >> 7;             // group 0..3
    const int gt  = tid & 127;            // thread in group
    const int wn  = gt >> 5;              // warp in group = 64-col band 0..3
    const int colBase = blockIdx.x * BN;
    const int barid = g + 1;

    // ---- A plumbing: 32 rows x 256B fp16 per tile; 4 thr/row, 64B each ----
    const int ra = gt >> 2, qa = gt & 3;
    const uint32_t aOff = (uint32_t)(ra * 272 + qa * 64);
    const int step = gridDim.y * NGROUPS;
    const int t0 = blockIdx.y * NGROUPS + g;

    auto ISSUE_A = [&](int t, int b) {
        const __half* gA = g_embedH + ((size_t)t * BMG + ra) * C_DIM + qa * 32;
        uint32_t d = sb + SM_A(g, b) + aOff;
#pragma unroll
        for (int j = 0; j < 4; j++) cp_async16(d + j * 16, gA + j * 8);
        CP_COMMIT();
    };
    if (t0 < nRowTiles) ISSUE_A(t0, 0);   // in flight during the B prologue below

    // ---- prologue: normalize B tile from raw fp32 P into smem fp16 ----
    // 2 threads/row: rb = tid>>1 (0..255), hb = tid&1 (64 floats each).
    {
        const int rb = tid >> 1, hb = tid & 1;
        const float4* gP = reinterpret_cast<const float4*>(
            P + (size_t)(colBase + rb) * C_DIM + hb * 64);
        float s = 0.0f;
#pragma unroll
        for (int j = 0; j < 16; j++) {
            float4 v = gP[j];
            s += v.x * v.x + v.y * v.y + v.z * v.z + v.w * v.w;
        }
        s += __shfl_xor_sync(0xFFFFFFFFu, s, 1);   // pair (2r, 2r+1): adjacent lanes
        float inv = 1.0f / fmaxf(sqrtf(s), EPS);
        __half* dstB = reinterpret_cast<__half*>(smem + SM_B) + rb * LDH + hb * 64;
#pragma unroll
        for (int j = 0; j < 8; j++) {              // reload (L1 hit), convert, STS
            float4 v0 = gP[j * 2 + 0];
            float4 v1 = gP[j * 2 + 1];
            uint4 pk;
            pk.x = h2u(__floats2half2_rn(v0.x * inv, v0.y * inv));
            pk.y = h2u(__floats2half2_rn(v0.z * inv, v0.w * inv));
            pk.z = h2u(__floats2half2_rn(v1.x * inv, v1.y * inv));
            pk.w = h2u(__floats2half2_rn(v1.z * inv, v1.w * inv));
            reinterpret_cast<uint4*>(dstB)[j] = pk;
        }
    }

    CP_WAIT0();
    __syncthreads();                      // B (STS) + A(t0) (cp.async) visible

    const __half* Abuf[2] = {
        reinterpret_cast<const __half*>(smem + SM_A(g, 0)),
        reinterpret_cast<const __half*>(smem + SM_A(g, 1))
    };
    int buf = 0;

    for (int t = t0; t < nRowTiles; t += step) {
        const bool hasNext = (t + step) < nRowTiles;
        if (hasNext) ISSUE_A(t + step, buf ^ 1);   // other buffer: no WAR

        const __half* A_h = Abuf[buf];

        // ---- MMA(t): warp tile 32x64 = 2x4 m16n16k16 ----
        wmma::fragment<wmma::accumulator, 16, 16, 16, float> acc[2][4];
#pragma unroll
        for (int i = 0; i < 2; i++)
#pragma unroll
            for (int j = 0; j < 4; j++) wmma::fill_fragment(acc[i][j], 0.0f);

#pragma unroll
        for (int kk = 0; kk < 8; kk++) {
            wmma::fragment<wmma::matrix_a, 16, 16, 16, __half, wmma::row_major> a[2];
            wmma::fragment<wmma::matrix_b, 16, 16, 16, __half, wmma::col_major> b[4];
#pragma unroll
            for (int i = 0; i < 2; i++)
                wmma::load_matrix_sync(a[i], A_h + (i * 16) * LDH + kk * 16, LDH);
#pragma unroll
            for (int j = 0; j < 4; j++)
                wmma::load_matrix_sync(b[j], B_h + (wn * 64 + j * 16) * LDH + kk * 16, LDH);
#pragma unroll
            for (int i = 0; i < 2; i++)
#pragma unroll
                for (int j = 0; j < 4; j++)
                    wmma::mma_sync(acc[i][j], a[i], b[j], acc[i][j]);
        }

        // ---- epilogue: -(1-cos)^2, direct store (proven path) ----
        float* outBase = out + ((size_t)t * BMG) * Kout + colBase + wn * 64;
#pragma unroll
        for (int i = 0; i < 2; i++)
#pragma unroll
            for (int j = 0; j < 4; j++) {
#pragma unroll
                for (int e = 0; e < acc[i][j].num_elements; e++) {
                    float d = 1.0f - acc[i][j].x[e];
                    acc[i][j].x[e] = -(d * d);
                }
                wmma::store_matrix_sync(outBase + (size_t)(i * 16) * Kout + j * 16,
                                        acc[i][j], Kout, wmma::mem_row_major);
            }

        if (hasNext) {
            CP_WAIT0();                   // A(t+step) landed (this thread)
            BAR_G(barid);                 // visible group-wide; MMA A reads done
        }
        buf ^= 1;
    }
}

// ======================= launcher =======================
extern "C" void kernel_launch(void* const* d_in, const int* in_sizes, int n_in,
                              void* d_out, int out_size) {
    const float* E = (const float*)d_in[0];
    const float* P = (const float*)d_in[1];
    float* out = (float*)d_out;

    const int N = in_sizes[0] / C_DIM;   // 131072
    const int K = in_sizes[1] / C_DIM;   // 512

    e_norm_fp16_kernel<<<(N * 32 + 255) / 256, 256>>>(E, N);

    static int sms = 0;
    if (!sms) {
        cudaDeviceGetAttribute(&sms, cudaDevAttrMultiProcessorCount, 0);
        cudaFuncSetAttribute(hsproto_gemm_kernel,
                             cudaFuncAttributeMaxDynamicSharedMemorySize, SMEM_TOTAL);
    }
    const int nColTiles = K / BN;                 // 2
    int stripe = sms / nColTiles;                 // 76
    if (stripe < 1) stripe = 1;
    const int nRowTiles = N / BMG;                // 4096

    dim3 grid(nColTiles, stripe);
    hsproto_gemm_kernel<<<grid, NTHREADS, SMEM_TOTAL>>>(P, out, nRowTiles, K);
}